// round 10
// baseline (speedup 1.0000x reference)
#include <cuda_runtime.h>
#include <cuda_fp16.h>
#include <cstdint>

#define NHID    128
#define K2      256
#define TILE_E  32
#define THREADS 256

// edge tile: fp16, padded rows of 264 halves = 528 B (odd 16B count -> conflict-free ldmatrix)
#define ERSTR   528

// ---- SMEM layout (bytes) ----
// [0, 65536) holds W1^T fp16 (init only); reused afterwards:
#define SM_W1    0
#define SM_E0    0         // 32 x 528 = 16896
#define SM_E1    16896     // ends 33792
#define SM_PART  33792     // 2 bufs x (8 warps x 32 edges) f32 = 2048
#define SM_TOTAL 65536

__device__ __forceinline__ uint32_t smem_u32(const void* p) {
    uint32_t a;
    asm("{ .reg .u64 t; cvta.to.shared.u64 t, %1; cvt.u32.u64 %0, t; }" : "=r"(a) : "l"(p));
    return a;
}
__device__ __forceinline__ void ldsm_x4(uint32_t addr, uint32_t r[4]) {
    asm volatile("ldmatrix.sync.aligned.m8n8.x4.shared.b16 {%0,%1,%2,%3}, [%4];"
                 : "=r"(r[0]), "=r"(r[1]), "=r"(r[2]), "=r"(r[3]) : "r"(addr));
}
__device__ __forceinline__ void mma_fp16(float c[4], const uint32_t a[4], uint32_t b0, uint32_t b1) {
    asm volatile("mma.sync.aligned.m16n8k16.row.col.f32.f16.f16.f32 "
                 "{%0,%1,%2,%3}, {%4,%5,%6,%7}, {%8,%9}, {%0,%1,%2,%3};"
                 : "+f"(c[0]), "+f"(c[1]), "+f"(c[2]), "+f"(c[3])
                 : "r"(a[0]), "r"(a[1]), "r"(a[2]), "r"(a[3]), "r"(b0), "r"(b1));
}

// int32 data -> stride 1; int64 (LE, values < 1e5) -> every odd word 0 -> stride 2
__device__ __forceinline__ int detect_idx_stride(const int* p, int n_words) {
    int stride = 2;
    #pragma unroll 1
    for (int i = 1; i < n_words; i += 2)
        if (p[i] != 0) { stride = 1; break; }
    return stride;
}

__global__ void __launch_bounds__(THREADS, 2)
mlp_decoder_hmma6_kernel(const float* __restrict__ inputs,
                         const int* __restrict__ x_idx,
                         const int* __restrict__ y_idx,
                         const float* __restrict__ W1,
                         const float* __restrict__ bias1,
                         const float* __restrict__ W2,
                         const float* __restrict__ bias2,
                         float* __restrict__ out,
                         int n_edges, int n_tiles)
{
    extern __shared__ char smem[];
    const uint32_t sb  = smem_u32(smem);
    const int tid  = threadIdx.x;
    const int lane = tid & 31;
    const int wid  = tid >> 5;    // warp owns output cols [wid*16, wid*16+16)

    const int probe_n = (n_edges >= 64) ? 128 : (2 * n_edges);
    const int istride = detect_idx_stride(x_idx, probe_n);

    // ---- init: W1 -> fp16 W1^T[n][k] in smem, XOR-swizzled 16B chunks ----
    for (int i = tid; i < NHID * K2; i += THREADS) {
        int n = i & (NHID - 1);
        int k = i >> 7;
        __half h = __float2half_rn(W1[k * NHID + n]);
        uint32_t off = (uint32_t)n * 512u + (uint32_t)(((k >> 3) ^ (n & 7)) << 4)
                     + (uint32_t)(k & 7) * 2u;
        *(__half*)(smem + SM_W1 + off) = h;
    }
    __syncthreads();

    // ---- per-warp A fragments (W1 cols 16*wid..+16, all K) into registers ----
    uint32_t aF[16][4];
    {
        uint32_t row = (uint32_t)(wid * 16 + (lane & 15));
        uint32_t rsw = (row & 7);
        #pragma unroll
        for (int kc = 0; kc < 16; kc++) {
            uint32_t chunk = (uint32_t)(2 * kc) + (uint32_t)(lane >> 4);
            uint32_t addr = sb + SM_W1 + row * 512u + ((chunk ^ rsw) << 4);
            ldsm_x4(addr, aF[kc]);
        }
    }
    const int j0 = wid * 16 + (lane >> 2);
    const int j1 = j0 + 8;
    const float b10 = bias1[j0], b11 = bias1[j1];
    const float w20 = W2[j0],    w21 = W2[j1];
    const float b2v = bias2[0];
    __syncthreads();   // W1 region free -> edge tiles

    // edge B-frag ldsm addressing (shared-space offsets only for ldmatrix)
    const uint32_t row_l = (uint32_t)((lane & 7) + ((lane >> 4) << 3));
    const uint32_t kb    = (uint32_t)((lane >> 3) & 1);
    const uint32_t ebL   = row_l * ERSTR + kb * 16u;

    // gather geometry: 32 rows x 64 16B-slots; 8 slots/thread
    const int c4   = tid & 63;
    const int row0 = tid >> 6;
    const int  src4 = c4 & 31;
    const int* idx_base = (c4 < 32) ? x_idx : y_idx;
    const uint32_t stoff = (uint32_t)c4 * 8u;

    const int stride_t = (int)gridDim.x;

    // ---- prologue ----
    float4 st[8];
    {   // gather + convert + store tile t0 into E0 (generic pointer stores)
        int e0 = blockIdx.x * TILE_E;
        #pragma unroll
        for (int it = 0; it < 8; it++) {
            int e = e0 + row0 + it * 4;
            int es = (e < n_edges) ? e : 0;
            int node = __ldg(idx_base + (size_t)es * istride);
            float4 v = __ldg((const float4*)(inputs + (size_t)node * NHID) + src4);
            __half2 h0 = __float22half2_rn(make_float2(v.x, v.y));
            __half2 h1 = __float22half2_rn(make_float2(v.z, v.w));
            *(uint2*)(smem + SM_E0 + (uint32_t)(row0 + it * 4) * ERSTR + stoff) =
                make_uint2(*(uint32_t*)&h0, *(uint32_t*)&h1);
        }
    }
    {   // gather tile t1 into regs
        int ntile = blockIdx.x + stride_t;
        if (ntile < n_tiles) {
            int ne0 = ntile * TILE_E;
            #pragma unroll
            for (int it = 0; it < 8; it++) {
                int e = ne0 + row0 + it * 4;
                int es = (e < n_edges) ? e : 0;
                int node = __ldg(idx_base + (size_t)es * istride);
                st[it] = __ldg((const float4*)(inputs + (size_t)node * NHID) + src4);
            }
        }
    }
    __syncthreads();   // E0 ready

    int cnt = 0;
    for (int tile = blockIdx.x; tile < n_tiles; tile += stride_t, cnt++) {
        const int e0 = tile * TILE_E;
        const int b  = cnt & 1;
        const uint32_t EcurS = sb + (b ? (uint32_t)SM_E1 : (uint32_t)SM_E0);  // shared addr (ldsm)
        char* EaltP = smem + (b ? SM_E0 : SM_E1);                             // generic ptr (STS)
        float* partb = (float*)(smem + SM_PART + (uint32_t)b * 1024u);

        // ---- MMA: 16 kc x (2 ldsm + 4 mma); A from registers ----
        float c[4][4];
        #pragma unroll
        for (int et = 0; et < 4; et++)
            #pragma unroll
            for (int j = 0; j < 4; j++) c[et][j] = 0.f;

        const uint32_t eb0 = EcurS + ebL;
        const uint32_t eb1 = eb0 + 16u * ERSTR;
        #pragma unroll
        for (int kc = 0; kc < 16; kc++) {
            uint32_t f0[4], f1[4];
            ldsm_x4(eb0 + (uint32_t)kc * 32u, f0);
            ldsm_x4(eb1 + (uint32_t)kc * 32u, f1);
            mma_fp16(c[0], aF[kc], f0[0], f0[1]);
            mma_fp16(c[1], aF[kc], f0[2], f0[3]);
            mma_fp16(c[2], aF[kc], f1[0], f1[1]);
            mma_fp16(c[3], aF[kc], f1[2], f1[3]);
        }

        // ---- convert + store tile t+1 into the other buffer (overlaps peers' MMA) ----
        if (tile + stride_t < n_tiles) {
            #pragma unroll
            for (int it = 0; it < 8; it++) {
                float4 v = st[it];
                __half2 h0 = __float22half2_rn(make_float2(v.x, v.y));
                __half2 h1 = __float22half2_rn(make_float2(v.z, v.w));
                *(uint2*)(EaltP + (uint32_t)(row0 + it * 4) * ERSTR + stoff) =
                    make_uint2(*(uint32_t*)&h0, *(uint32_t*)&h1);
            }
        }

        // ---- prefetch tile t+2 (LDG latency hides under sync + next MMA) ----
        {
            int ptile = tile + 2 * stride_t;
            if (ptile < n_tiles) {
                int pe0 = ptile * TILE_E;
                #pragma unroll
                for (int it = 0; it < 8; it++) {
                    int e = pe0 + row0 + it * 4;
                    int es = (e < n_edges) ? e : 0;
                    int node = __ldg(idx_base + (size_t)es * istride);
                    st[it] = __ldg((const float4*)(inputs + (size_t)node * NHID) + src4);
                }
            }
        }

        // ---- epilogue partials ----
        #pragma unroll
        for (int et = 0; et < 4; et++) {
            float pa = fmaf(fmaxf(c[et][0] + b10, 0.f), w20,
                            fmaxf(c[et][2] + b11, 0.f) * w21);
            float pb = fmaf(fmaxf(c[et][1] + b10, 0.f), w20,
                            fmaxf(c[et][3] + b11, 0.f) * w21);
            pa += __shfl_xor_sync(0xffffffffu, pa, 4, 32);
            pa += __shfl_xor_sync(0xffffffffu, pa, 8, 32);
            pa += __shfl_xor_sync(0xffffffffu, pa, 16, 32);
            pb += __shfl_xor_sync(0xffffffffu, pb, 4, 32);
            pb += __shfl_xor_sync(0xffffffffu, pb, 8, 32);
            pb += __shfl_xor_sync(0xffffffffu, pb, 16, 32);
            if (lane < 4) {
                int ea = et * 8 + 2 * lane;
                partb[wid * 32 + ea]     = pa;
                partb[wid * 32 + ea + 1] = pb;
            }
        }
        __syncthreads();   // ONE barrier: E[alt] ready, part[b] ready

        // ---- output pass (rotating warp) ----
        if (wid == (cnt & 7)) {
            int e = e0 + lane;
            if (e < n_edges) {
                float s = b2v;
                #pragma unroll
                for (int w = 0; w < 8; w++) s += partb[w * 32 + lane];
                out[e] = 1.f / (1.f + __expf(-s));
            }
        }
    }
}

extern "C" void kernel_launch(void* const* d_in, const int* in_sizes, int n_in,
                              void* d_out, int out_size) {
    const float* inputs = (const float*)d_in[0];
    const int*   xi     = (const int*)d_in[1];
    const int*   yi     = (const int*)d_in[2];
    const float* W1     = (const float*)d_in[3];
    const float* b1     = (const float*)d_in[4];
    const float* W2     = (const float*)d_in[5];
    const float* b2     = (const float*)d_in[6];
    float* out = (float*)d_out;

    const int n_edges = in_sizes[1];
    const int n_tiles = (n_edges + TILE_E - 1) / TILE_E;

    cudaFuncSetAttribute(mlp_decoder_hmma6_kernel,
                         cudaFuncAttributeMaxDynamicSharedMemorySize, SM_TOTAL);

    int dev = 0, nsm = 148;
    cudaGetDevice(&dev);
    cudaDeviceGetAttribute(&nsm, cudaDevAttrMultiProcessorCount, dev);
    int grid = 2 * nsm;
    if (grid > n_tiles) grid = n_tiles;

    mlp_decoder_hmma6_kernel<<<grid, THREADS, SM_TOTAL>>>(
        inputs, xi, yi, W1, b1, W2, b2, out, n_edges, n_tiles);
}